// round 4
// baseline (speedup 1.0000x reference)
#include <cuda_runtime.h>
#include <cstdint>

#define NH 32     // hidden
#define RK 6      // rank
#define BB 256    // batch
#define TT 2048   // time
#define DI 64     // input dim
#define DO 32     // output dim

#define NCH  16           // time chunks
#define SPC  (TT / NCH)   // 128 steps per chunk
#define TILES_PER_CHUNK (BB * SPC / 64)   // 512
#define RNN_BLOCKS 32     // 8 warps each -> 256 batch chains

// 64 MB scratch for pre-scaled x-projection (device global: allocation-free)
__device__ float    g_xp[(size_t)BB * TT * NH];
__device__ unsigned g_ctr[NCH];

#define L2E2 2.885390081777926815f   // 2*log2(e)

// Packed fp32x2 ops (Blackwell)
__device__ __forceinline__ float2 fma2(const float2 a, const float2 b, const float2 c) {
    float2 d;
    asm("fma.rn.f32x2 %0, %1, %2, %3;"
        : "=l"(*(unsigned long long*)&d)
        : "l"(*(const unsigned long long*)&a),
          "l"(*(const unsigned long long*)&b),
          "l"(*(const unsigned long long*)&c));
    return d;
}
__device__ __forceinline__ float2 add2(const float2 a, const float2 b) {
    float2 d;
    asm("add.rn.f32x2 %0, %1, %2;"
        : "=l"(*(unsigned long long*)&d)
        : "l"(*(const unsigned long long*)&a),
          "l"(*(const unsigned long long*)&b));
    return d;
}

__global__ void reset_kernel() {
    if (threadIdx.x < NCH) g_ctr[threadIdx.x] = 0u;
}

// Shared memory: xproj path and rnn path never coexist in one block.
union Smem {
    struct {
        float u[64 * DI];          // 16 KB
        float Wsm[NH][DI + 1];     // padded, 8.3 KB
    } xp;
    float4 vbuf[8][2][NH / 4];     // [warp][double-buffer][v as float4]
};

// ---------------------------------------------------------------------------
// Fused kernel.
//   blocks [0, 32):        RNN consumer warps (1 batch per warp)
//   blocks [32, 32+8192):  xproj producer tiles, ordered by time-chunk.
// Producers: g_xp[b,t,n] = L2E2*(u[b,t]·W_in[n] + bias[n]); bump chunk counter.
// Consumers: sequential recurrence; per chunk, spin until counter full.
//   p' = 2log2e*(W_rec h):  p <- 0.9 p + (0.1*2log2e*W_rec)·v
//   q  = W_out h_{t+1}:     q <- 0.9 q + (0.1*W_out)·v ;  y_t = q + b_out
//   h  <- 0.9 h + 0.1 v  (h_final)
// ---------------------------------------------------------------------------
__global__ void __launch_bounds__(256) fused_kernel(
    const float* __restrict__ inp, const float* __restrict__ Win,
    const float* __restrict__ bias,
    const float* __restrict__ m, const float* __restrict__ nv,
    const float* __restrict__ Mm, const float* __restrict__ Nm,
    const float* __restrict__ Wout, const float* __restrict__ bout,
    float* __restrict__ out, float* __restrict__ hfin)
{
    __shared__ Smem sm;
    const int tid = threadIdx.x;

    if (blockIdx.x >= RNN_BLOCKS) {
        // ----------------- PRODUCER: xproj tile (64 rows) -----------------
        const int idx  = blockIdx.x - RNN_BLOCKS;
        const int c    = idx >> 9;            // chunk
        const int w    = idx & 511;
        const int b    = w >> 1;
        const int half = w & 1;
        const size_t row0 = (size_t)b * TT + (size_t)c * SPC + half * 64;

        for (int i = tid; i < NH * DI; i += 256)
            sm.xp.Wsm[i / DI][i % DI] = Win[i];

        const float4* gs = (const float4*)(inp + row0 * DI);
        float4* sd = (float4*)sm.xp.u;
        #pragma unroll
        for (int k2 = 0; k2 < 4; k2++) sd[tid + 256 * k2] = gs[tid + 256 * k2];
        __syncthreads();

        const int n_ = tid & 31;
        const int rg = tid >> 5;

        float2 w2[DI / 2];
        #pragma unroll
        for (int i = 0; i < DI; i += 2)
            w2[i / 2] = make_float2(sm.xp.Wsm[n_][i], sm.xp.Wsm[n_][i + 1]);

        float2 acc[8];
        #pragma unroll
        for (int r = 0; r < 8; r++) acc[r] = make_float2(0.f, 0.f);

        #pragma unroll
        for (int i4 = 0; i4 < DI / 4; i4++) {
            const float2 wlo = w2[2 * i4 + 0];
            const float2 whi = w2[2 * i4 + 1];
            #pragma unroll
            for (int r = 0; r < 8; r++) {
                const float4 u4 = *(const float4*)&sm.xp.u[(rg * 8 + r) * DI + i4 * 4];
                acc[r] = fma2(wlo, make_float2(u4.x, u4.y), acc[r]);
                acc[r] = fma2(whi, make_float2(u4.z, u4.w), acc[r]);
            }
        }

        const float bn = bias[n_];
        #pragma unroll
        for (int r = 0; r < 8; r++)
            g_xp[(row0 + rg * 8 + r) * NH + n_] = L2E2 * (acc[r].x + acc[r].y + bn);

        __syncthreads();
        if (tid == 0) {
            __threadfence();                 // cumulative: block's stores -> gpu scope
            atomicAdd(&g_ctr[c], 1u);
        }
        return;
    }

    // --------------------- CONSUMER: RNN chain --------------------------
    const int wid = tid >> 5;
    const int l   = tid & 31;
    const int b   = blockIdx.x * 8 + wid;

    // Scaled W_rec row l: wr[k] = 0.1*2log2e*(m_l n_k + sum_j M_lj N_kj)
    float Ml[RK];
    const float ml = m[l];
    #pragma unroll
    for (int j = 0; j < RK; j++) Ml[j] = Mm[l * RK + j];
    float2 w2[NH / 2], o2[NH / 2];
    #pragma unroll
    for (int k = 0; k < NH; k += 2) {
        float s0 = ml * nv[k], s1 = ml * nv[k + 1];
        #pragma unroll
        for (int j = 0; j < RK; j++) {
            s0 = fmaf(Ml[j], Nm[k * RK + j], s0);
            s1 = fmaf(Ml[j], Nm[(k + 1) * RK + j], s1);
        }
        w2[k / 2] = make_float2(0.1f * L2E2 * s0, 0.1f * L2E2 * s1);
        o2[k / 2] = make_float2(0.1f * Wout[l * NH + k], 0.1f * Wout[l * NH + k + 1]);
    }
    const float bo = bout[l];

    const float* xp = g_xp + (size_t)b * TT * NH + l;
    float* yo = out + (size_t)b * TT * DO + l;

    float p = 0.f, q = 0.f, h = 0.f;

    for (int c = 0; c < NCH; c++) {
        // Wait for this chunk's x-projection (volatile poll + fence = acquire)
        if (l == 0) {
            if (*((volatile unsigned*)&g_ctr[c]) < TILES_PER_CHUNK) {
                while (*((volatile unsigned*)&g_ctr[c]) < TILES_PER_CHUNK)
                    __nanosleep(200);
            }
        }
        __syncwarp();
        __threadfence();

        const int t0 = c * SPC;
        float xb[8];
        #pragma unroll
        for (int i = 0; i < 8; i++) xb[i] = xp[(size_t)(t0 + i) * NH];

        for (int tt = 0; tt < SPC; tt += 8) {
            #pragma unroll
            for (int s = 0; s < 8; s++) {
                const int t   = t0 + tt + s;
                const int buf = s & 1;
                const float x = xb[s];
                if (tt + 8 < SPC) xb[s] = xp[(size_t)(t + 8) * NH];

                const float pre = p + x;   // pre-scaled by 2log2e
                float e;
                asm("ex2.approx.f32 %0, %1;" : "=f"(e) : "f"(pre));
                float r;
                asm("rcp.approx.f32 %0, %1;" : "=f"(r) : "f"(e + 1.0f));
                const float v = fmaf(-2.0f, r, 1.0f);

                ((float*)sm.vbuf[wid][buf])[l] = v;
                __syncwarp();

                float2 ap[4], aq[4];
                #pragma unroll
                for (int i = 0; i < 4; i++) { ap[i] = make_float2(0.f, 0.f); aq[i] = ap[i]; }
                #pragma unroll
                for (int j = 0; j < NH / 4; j++) {
                    const float4 v4 = sm.vbuf[wid][buf][j];
                    const float2 lo = make_float2(v4.x, v4.y);
                    const float2 hi = make_float2(v4.z, v4.w);
                    ap[j & 3] = fma2(w2[2 * j + 0], lo, ap[j & 3]);
                    ap[j & 3] = fma2(w2[2 * j + 1], hi, ap[j & 3]);
                    aq[j & 3] = fma2(o2[2 * j + 0], lo, aq[j & 3]);
                    aq[j & 3] = fma2(o2[2 * j + 1], hi, aq[j & 3]);
                }
                const float2 sp2 = add2(add2(ap[0], ap[1]), add2(ap[2], ap[3]));
                const float2 sq2 = add2(add2(aq[0], aq[1]), add2(aq[2], aq[3]));

                p = fmaf(0.9f, p, sp2.x + sp2.y);
                q = fmaf(0.9f, q, sq2.x + sq2.y);
                h = fmaf(0.9f, h, 0.1f * v);

                yo[(size_t)t * DO] = q + bo;
            }
        }
    }

    if (hfin) hfin[b * NH + l] = h;
}

// ---------------------------------------------------------------------------
extern "C" void kernel_launch(void* const* d_in, const int* in_sizes, int n_in,
                              void* d_out, int out_size) {
    const float* inputs = (const float*)d_in[0];
    const float* W_in   = (const float*)d_in[1];
    const float* m_     = (const float*)d_in[2];
    const float* n_     = (const float*)d_in[3];
    const float* M_     = (const float*)d_in[4];
    const float* Nm_    = (const float*)d_in[5];
    const float* bias   = (const float*)d_in[6];
    const float* Wout   = (const float*)d_in[7];
    const float* bout   = (const float*)d_in[8];

    float* out = (float*)d_out;
    float* hf = nullptr;
    const long long need = (long long)BB * TT * NH + (long long)BB * NH;
    if ((long long)out_size >= need)
        hf = out + (size_t)BB * TT * NH;

    reset_kernel<<<1, 32>>>();
    fused_kernel<<<RNN_BLOCKS + NCH * TILES_PER_CHUNK, 256>>>(
        inputs, W_in, bias, m_, n_, M_, Nm_, Wout, bout, out, hf);
}

// round 5
// speedup vs baseline: 3.9670x; 3.9670x over previous
#include <cuda_runtime.h>
#include <cstdint>

#define NH 32     // hidden
#define RK 6      // rank
#define BB 256    // batch
#define TT 2048   // time
#define DI 64     // input dim
#define DO 32     // output dim

// 64 MB scratch for pre-scaled x-projection (device global: allocation-free)
__device__ float g_xp[(size_t)BB * TT * NH];

#define L2E2 2.885390081777926815f   // 2*log2(e)

// Packed fp32x2 ops (Blackwell)
__device__ __forceinline__ float2 fma2(const float2 a, const float2 b, const float2 c) {
    float2 d;
    asm("fma.rn.f32x2 %0, %1, %2, %3;"
        : "=l"(*(unsigned long long*)&d)
        : "l"(*(const unsigned long long*)&a),
          "l"(*(const unsigned long long*)&b),
          "l"(*(const unsigned long long*)&c));
    return d;
}
__device__ __forceinline__ float2 add2(const float2 a, const float2 b) {
    float2 d;
    asm("add.rn.f32x2 %0, %1, %2;"
        : "=l"(*(unsigned long long*)&d)
        : "l"(*(const unsigned long long*)&a),
          "l"(*(const unsigned long long*)&b));
    return d;
}

// ---------------------------------------------------------------------------
// Kernel 1: g_xp[b,t,n] = L2E2 * (sum_i inputs[b,t,i]*W_in[n,i] + bias[n])
// (identical to the 90us R3 version)
// ---------------------------------------------------------------------------
__global__ void __launch_bounds__(256) xproj_kernel(
    const float* __restrict__ inp, const float* __restrict__ Win,
    const float* __restrict__ bias)
{
    __shared__ float u[64 * DI];
    __shared__ float Wsm[NH][DI + 1];

    const int tid = threadIdx.x;

    for (int idx = tid; idx < NH * DI; idx += 256)
        Wsm[idx / DI][idx % DI] = Win[idx];

    const size_t base = (size_t)blockIdx.x * 64 * DI;
    const float4* gs = (const float4*)(inp + base);
    float4* sd = (float4*)u;
    #pragma unroll
    for (int k2 = 0; k2 < 4; k2++) sd[tid + 256 * k2] = gs[tid + 256 * k2];
    __syncthreads();

    const int n_ = tid & 31;
    const int rg = tid >> 5;

    float2 w2[DI / 2];
    #pragma unroll
    for (int i = 0; i < DI; i += 2)
        w2[i / 2] = make_float2(Wsm[n_][i], Wsm[n_][i + 1]);

    float2 acc[8];
    #pragma unroll
    for (int r = 0; r < 8; r++) acc[r] = make_float2(0.f, 0.f);

    #pragma unroll
    for (int i4 = 0; i4 < DI / 4; i4++) {
        const float2 wlo = w2[2 * i4 + 0];
        const float2 whi = w2[2 * i4 + 1];
        #pragma unroll
        for (int r = 0; r < 8; r++) {
            const float4 u4 = *(const float4*)&u[(rg * 8 + r) * DI + i4 * 4];
            acc[r] = fma2(wlo, make_float2(u4.x, u4.y), acc[r]);
            acc[r] = fma2(whi, make_float2(u4.z, u4.w), acc[r]);
        }
    }

    const float bn = bias[n_];
    const size_t rowbase = (size_t)blockIdx.x * 64;
    #pragma unroll
    for (int r = 0; r < 8; r++)
        g_xp[(rowbase + rg * 8 + r) * NH + n_] = L2E2 * (acc[r].x + acc[r].y + bn);
}

// ---------------------------------------------------------------------------
// Kernel 2: sequential recurrence + fused output. One warp per block, one
// batch per warp; lane l owns hidden unit l AND output unit l.
//
// Identity: tanh = 1 - 2r, r = 1/(exp2(pre')+1), pre' scaled by 2log2e.
// Lanes broadcast r via smem; weights pre-folded:
//   wr2[k]  = -0.2*L2E2*W_rec[l,k],  wrsum = 0.1*L2E2*sum_k W_rec[l,k]
//   wo2[k]  = -0.2*W_out[l,k],       wosum = 0.1*sum_k W_out[l,k]
// Per step:
//   p <- (0.9p + wrsum) + sum_k wr2[k]*r_k        (base computed during MUFUs)
//   q <- (0.9q + wosum) + sum_k wo2[k]*r_k ;  y_t = q + b_out
//   h <- (0.9h + 0.1) - 0.2*r_l                   (h_final only)
// ---------------------------------------------------------------------------
__global__ void __launch_bounds__(32) rnn_kernel(
    const float* __restrict__ m, const float* __restrict__ nv,
    const float* __restrict__ Mm, const float* __restrict__ Nm,
    const float* __restrict__ Wout, const float* __restrict__ bout,
    float* __restrict__ out, float* __restrict__ hfin)
{
    __shared__ float4 vbuf[2][NH / 4];

    const int b = blockIdx.x;
    const int l = threadIdx.x;

    // Build folded weight rows for lane l
    float Ml[RK];
    const float ml = m[l];
    #pragma unroll
    for (int j = 0; j < RK; j++) Ml[j] = Mm[l * RK + j];

    float2 wr2[NH / 2], wo2[NH / 2];
    float wrsum = 0.f, wosum = 0.f;
    #pragma unroll
    for (int k = 0; k < NH; k += 2) {
        float s0 = ml * nv[k], s1 = ml * nv[k + 1];
        #pragma unroll
        for (int j = 0; j < RK; j++) {
            s0 = fmaf(Ml[j], Nm[k * RK + j], s0);
            s1 = fmaf(Ml[j], Nm[(k + 1) * RK + j], s1);
        }
        wrsum += s0 + s1;
        wr2[k / 2] = make_float2(-0.2f * L2E2 * s0, -0.2f * L2E2 * s1);
        const float o0 = Wout[l * NH + k], o1 = Wout[l * NH + k + 1];
        wosum += o0 + o1;
        wo2[k / 2] = make_float2(-0.2f * o0, -0.2f * o1);
    }
    wrsum *= 0.1f * L2E2;
    wosum *= 0.1f;
    const float bo = bout[l];

    const float* xp = g_xp + (size_t)b * TT * NH + l;
    float* yo = out + (size_t)b * TT * DO + l;

    float p = 0.f, q = 0.f, h = 0.f;

    float xb[8];
    #pragma unroll
    for (int i = 0; i < 8; i++) xb[i] = xp[(size_t)i * NH];

    for (int t = 0; t < TT; t += 8) {
        #pragma unroll
        for (int s = 0; s < 8; s++) {
            const int t0 = t + s;
            const int buf = s & 1;
            const float x = xb[s];
            if (t + 8 < TT) xb[s] = xp[(size_t)(t0 + 8) * NH];

            // chain: pre -> ex2 -> +1 -> rcp -> r
            const float pre = p + x;
            float e;
            asm("ex2.approx.f32 %0, %1;" : "=f"(e) : "f"(pre));
            float r;
            asm("rcp.approx.f32 %0, %1;" : "=f"(r) : "f"(e + 1.0f));

            // off-chain work hidden under MUFU latency
            const float pbase = fmaf(0.9f, p, wrsum);
            const float qbase = fmaf(0.9f, q, wosum);
            h = fmaf(0.9f, h, 0.1f);

            ((float*)vbuf[buf])[l] = r;
            __syncwarp();
            h = fmaf(-0.2f, r, h);

            float2 ap[4], aq[4];
            #pragma unroll
            for (int i = 0; i < 4; i++) { ap[i] = make_float2(0.f, 0.f); aq[i] = ap[i]; }
            #pragma unroll
            for (int j = 0; j < NH / 4; j++) {
                const float4 r4 = vbuf[buf][j];
                const float2 lo = make_float2(r4.x, r4.y);
                const float2 hi = make_float2(r4.z, r4.w);
                ap[j & 3] = fma2(wr2[2 * j + 0], lo, ap[j & 3]);
                ap[j & 3] = fma2(wr2[2 * j + 1], hi, ap[j & 3]);
                aq[j & 3] = fma2(wo2[2 * j + 0], lo, aq[j & 3]);
                aq[j & 3] = fma2(wo2[2 * j + 1], hi, aq[j & 3]);
            }
            const float2 sp2 = add2(add2(ap[0], ap[1]), add2(ap[2], ap[3]));
            const float2 sq2 = add2(add2(aq[0], aq[1]), add2(aq[2], aq[3]));

            p = pbase + (sp2.x + sp2.y);
            q = qbase + (sq2.x + sq2.y);

            yo[(size_t)t0 * DO] = q + bo;
        }
    }

    if (hfin) hfin[b * NH + l] = h;
}

// ---------------------------------------------------------------------------
extern "C" void kernel_launch(void* const* d_in, const int* in_sizes, int n_in,
                              void* d_out, int out_size) {
    const float* inputs = (const float*)d_in[0];
    const float* W_in   = (const float*)d_in[1];
    const float* m_     = (const float*)d_in[2];
    const float* n_     = (const float*)d_in[3];
    const float* M_     = (const float*)d_in[4];
    const float* Nm_    = (const float*)d_in[5];
    const float* bias   = (const float*)d_in[6];
    const float* Wout   = (const float*)d_in[7];
    const float* bout   = (const float*)d_in[8];

    float* out = (float*)d_out;
    float* hf = nullptr;
    const long long need = (long long)BB * TT * NH + (long long)BB * NH;
    if ((long long)out_size >= need)
        hf = out + (size_t)BB * TT * NH;

    xproj_kernel<<<BB * TT / 64, 256>>>(inputs, W_in, bias);
    rnn_kernel<<<BB, 32>>>(m_, n_, M_, Nm_, Wout, bout, out, hf);
}

// round 6
// speedup vs baseline: 6.0516x; 1.5255x over previous
#include <cuda_runtime.h>
#include <cstdint>

#define NH 32     // hidden
#define RK 6      // rank
#define BB 256    // batch
#define TT 2048   // time
#define DI 64     // input dim
#define DO 32     // output dim

#define RING  256
#define RINGM 255

// 64 MB scratch for pre-scaled x-projection (device global: allocation-free)
__device__ float g_xp[(size_t)BB * TT * NH];

#define L2E2 2.885390081777926815f   // 2*log2(e)

// Packed fp32x2 ops (Blackwell)
__device__ __forceinline__ float2 fma2(const float2 a, const float2 b, const float2 c) {
    float2 d;
    asm("fma.rn.f32x2 %0, %1, %2, %3;"
        : "=l"(*(unsigned long long*)&d)
        : "l"(*(const unsigned long long*)&a),
          "l"(*(const unsigned long long*)&b),
          "l"(*(const unsigned long long*)&c));
    return d;
}
__device__ __forceinline__ float2 add2(const float2 a, const float2 b) {
    float2 d;
    asm("add.rn.f32x2 %0, %1, %2;"
        : "=l"(*(unsigned long long*)&d)
        : "l"(*(const unsigned long long*)&a),
          "l"(*(const unsigned long long*)&b));
    return d;
}

// ---------------------------------------------------------------------------
// Kernel 1: g_xp[b,t,n] = L2E2 * (sum_i inputs[b,t,i]*W_in[n,i] + bias[n])
// (proven 90us version, unchanged)
// ---------------------------------------------------------------------------
__global__ void __launch_bounds__(256) xproj_kernel(
    const float* __restrict__ inp, const float* __restrict__ Win,
    const float* __restrict__ bias)
{
    __shared__ float u[64 * DI];
    __shared__ float Wsm[NH][DI + 1];

    const int tid = threadIdx.x;

    for (int idx = tid; idx < NH * DI; idx += 256)
        Wsm[idx / DI][idx % DI] = Win[idx];

    const size_t base = (size_t)blockIdx.x * 64 * DI;
    const float4* gs = (const float4*)(inp + base);
    float4* sd = (float4*)u;
    #pragma unroll
    for (int k2 = 0; k2 < 4; k2++) sd[tid + 256 * k2] = gs[tid + 256 * k2];
    __syncthreads();

    const int n_ = tid & 31;
    const int rg = tid >> 5;

    float2 w2[DI / 2];
    #pragma unroll
    for (int i = 0; i < DI; i += 2)
        w2[i / 2] = make_float2(Wsm[n_][i], Wsm[n_][i + 1]);

    float2 acc[8];
    #pragma unroll
    for (int r = 0; r < 8; r++) acc[r] = make_float2(0.f, 0.f);

    #pragma unroll
    for (int i4 = 0; i4 < DI / 4; i4++) {
        const float2 wlo = w2[2 * i4 + 0];
        const float2 whi = w2[2 * i4 + 1];
        #pragma unroll
        for (int r = 0; r < 8; r++) {
            const float4 u4 = *(const float4*)&u[(rg * 8 + r) * DI + i4 * 4];
            acc[r] = fma2(wlo, make_float2(u4.x, u4.y), acc[r]);
            acc[r] = fma2(whi, make_float2(u4.z, u4.w), acc[r]);
        }
    }

    const float bn = bias[n_];
    const size_t rowbase = (size_t)blockIdx.x * 64;
    #pragma unroll
    for (int r = 0; r < 8; r++)
        g_xp[(rowbase + rg * 8 + r) * NH + n_] = L2E2 * (acc[r].x + acc[r].y + bn);
}

// ---------------------------------------------------------------------------
// Kernel 2: warp-specialized recurrence. One block (64 thr) per batch chain.
//   Warp A (wid 0): critical p-recurrence, writes r_t to a smem ring.
//   Warp B (wid 1): trails A, computes q/h/y from the ring.
// tanh = 1 - 2r, r = 1/(exp2(pre')+1), pre' in 2log2e-scaled space.
// ---------------------------------------------------------------------------
__global__ void __launch_bounds__(64) rnn_kernel(
    const float* __restrict__ m, const float* __restrict__ nv,
    const float* __restrict__ Mm, const float* __restrict__ Nm,
    const float* __restrict__ Wout, const float* __restrict__ bout,
    float* __restrict__ out, float* __restrict__ hfin)
{
    __shared__ __align__(16) float ring[RING][NH];   // 32 KB
    __shared__ unsigned progress;   // steps produced by A
    __shared__ unsigned bdone;      // steps consumed by B

    const int b   = blockIdx.x;
    const int wid = threadIdx.x >> 5;
    const int l   = threadIdx.x & 31;

    if (threadIdx.x == 0) { progress = 0u; bdone = 0u; }
    __syncthreads();

    if (wid == 0) {
        // ================= WARP A: critical chain =================
        // wr2[k] = -0.2*L2E2*W_rec[l,k], wrsum = 0.1*L2E2*sum_k W_rec[l,k]
        float Ml[RK];
        const float ml = m[l];
        #pragma unroll
        for (int j = 0; j < RK; j++) Ml[j] = Mm[l * RK + j];

        float2 wr2[NH / 2];
        float wrsum = 0.f;
        #pragma unroll
        for (int k = 0; k < NH; k += 2) {
            float s0 = ml * nv[k], s1 = ml * nv[k + 1];
            #pragma unroll
            for (int j = 0; j < RK; j++) {
                s0 = fmaf(Ml[j], Nm[k * RK + j], s0);
                s1 = fmaf(Ml[j], Nm[(k + 1) * RK + j], s1);
            }
            wrsum += s0 + s1;
            wr2[k / 2] = make_float2(-0.2f * L2E2 * s0, -0.2f * L2E2 * s1);
        }
        wrsum *= 0.1f * L2E2;

        const float* xp = g_xp + (size_t)b * TT * NH + l;
        float p = 0.f;

        float xa[8], xn[8];
        #pragma unroll
        for (int i = 0; i < 8; i++) xa[i] = xp[(size_t)i * NH];

        for (int c = 0; c < TT / 8; c++) {
            const int t0 = c * 8;
            if (c + 1 < TT / 8) {
                #pragma unroll
                for (int i = 0; i < 8; i++) xn[i] = xp[(size_t)(t0 + 8 + i) * NH];
            }
            #pragma unroll
            for (int s = 0; s < 8; s++) {
                const int t = t0 + s;
                const float pre = p + xa[s];
                float e;
                asm("ex2.approx.f32 %0, %1;" : "=f"(e) : "f"(pre));
                float r;
                asm("rcp.approx.f32 %0, %1;" : "=f"(r) : "f"(e + 1.0f));

                const float pbase = fmaf(0.9f, p, wrsum);   // in MUFU shadow

                ring[t & RINGM][l] = r;
                __syncwarp();

                const float4* r4p = (const float4*)ring[t & RINGM];
                float2 ap0 = make_float2(0.f, 0.f), ap1 = ap0, ap2 = ap0, ap3 = ap0;
                #pragma unroll
                for (int j = 0; j < NH / 4; j++) {
                    const float4 r4 = r4p[j];
                    const float2 lo = make_float2(r4.x, r4.y);
                    const float2 hi = make_float2(r4.z, r4.w);
                    float2 acc = (j & 3) == 0 ? ap0 : (j & 3) == 1 ? ap1 : (j & 3) == 2 ? ap2 : ap3;
                    acc = fma2(wr2[2 * j + 0], lo, acc);
                    acc = fma2(wr2[2 * j + 1], hi, acc);
                    if ((j & 3) == 0) ap0 = acc; else if ((j & 3) == 1) ap1 = acc;
                    else if ((j & 3) == 2) ap2 = acc; else ap3 = acc;
                }
                const float2 sp2 = add2(add2(ap0, ap1), add2(ap2, ap3));
                p = pbase + (sp2.x + sp2.y);
            }
            #pragma unroll
            for (int i = 0; i < 8; i++) xa[i] = xn[i];

            if ((c & 3) == 3) {
                // publish: all A lanes fence (ring stores -> CTA scope), then flag
                __threadfence_block();
                __syncwarp();
                if (l == 0)
                    *(volatile unsigned*)&progress = (unsigned)(t0 + 8);
                // ring-overrun guard (B is faster; this never fires in practice)
                if (l == 0) {
                    while ((int)(t0 + 8) - (int)(*(volatile unsigned*)&bdone) > RING - 64)
                        __nanosleep(100);
                }
                __syncwarp();
            }
        }
    } else {
        // ================= WARP B: trailing q/h/y =================
        // wo2[k] = -0.2*W_out[l,k], wosum = 0.1*sum_k W_out[l,k]
        float2 wo2[NH / 2];
        float wosum = 0.f;
        #pragma unroll
        for (int k = 0; k < NH; k += 2) {
            const float o0 = Wout[l * NH + k], o1 = Wout[l * NH + k + 1];
            wosum += o0 + o1;
            wo2[k / 2] = make_float2(-0.2f * o0, -0.2f * o1);
        }
        wosum *= 0.1f;
        const float bo = bout[l];

        float* yo = out + (size_t)b * TT * DO + l;
        float q = 0.f, h = 0.f;

        for (int blk = 0; blk < TT / 32; blk++) {
            const int tend = (blk + 1) * 32;
            if (l == 0) {
                while ((int)(*(volatile unsigned*)&progress) < tend)
                    __nanosleep(150);
            }
            __syncwarp();
            __threadfence_block();   // acquire: ring writes visible

            for (int t = blk * 32; t < tend; t++) {
                const float4* r4p = (const float4*)ring[t & RINGM];
                float2 aq0 = make_float2(0.f, 0.f), aq1 = aq0, aq2 = aq0, aq3 = aq0;
                #pragma unroll
                for (int j = 0; j < NH / 4; j++) {
                    const float4 r4 = r4p[j];
                    const float2 lo = make_float2(r4.x, r4.y);
                    const float2 hi = make_float2(r4.z, r4.w);
                    float2 acc = (j & 3) == 0 ? aq0 : (j & 3) == 1 ? aq1 : (j & 3) == 2 ? aq2 : aq3;
                    acc = fma2(wo2[2 * j + 0], lo, acc);
                    acc = fma2(wo2[2 * j + 1], hi, acc);
                    if ((j & 3) == 0) aq0 = acc; else if ((j & 3) == 1) aq1 = acc;
                    else if ((j & 3) == 2) aq2 = acc; else aq3 = acc;
                }
                const float2 sq2 = add2(add2(aq0, aq1), add2(aq2, aq3));
                const float rl = ring[t & RINGM][l];

                q = fmaf(0.9f, q, wosum) + (sq2.x + sq2.y);
                h = fmaf(0.9f, h, 0.1f);
                h = fmaf(-0.2f, rl, h);

                yo[(size_t)t * DO] = q + bo;
            }

            if (l == 0) {
                __threadfence_block();
                *(volatile unsigned*)&bdone = (unsigned)tend;
            }
        }

        if (hfin) hfin[b * NH + l] = h;
    }
}

// ---------------------------------------------------------------------------
extern "C" void kernel_launch(void* const* d_in, const int* in_sizes, int n_in,
                              void* d_out, int out_size) {
    const float* inputs = (const float*)d_in[0];
    const float* W_in   = (const float*)d_in[1];
    const float* m_     = (const float*)d_in[2];
    const float* n_     = (const float*)d_in[3];
    const float* M_     = (const float*)d_in[4];
    const float* Nm_    = (const float*)d_in[5];
    const float* bias   = (const float*)d_in[6];
    const float* Wout   = (const float*)d_in[7];
    const float* bout   = (const float*)d_in[8];

    float* out = (float*)d_out;
    float* hf = nullptr;
    const long long need = (long long)BB * TT * NH + (long long)BB * NH;
    if ((long long)out_size >= need)
        hf = out + (size_t)BB * TT * NH;

    xproj_kernel<<<BB * TT / 64, 256>>>(inputs, W_in, bias);
    rnn_kernel<<<BB, 64>>>(m_, n_, M_, Nm_, Wout, bout, out, hf);
}